// round 2
// baseline (speedup 1.0000x reference)
#include <cuda_runtime.h>
#include <cstdint>

#define BB 128
#define TT 1024
#define DD 512

// Packed significant-region mask: 512 bits per batch.
__device__ unsigned int g_mask[BB][DD / 32];
// Normalized metadata (decoded from whatever storage layout the harness used).
__device__ int g_dom[BB];
__device__ int g_partner[BB];

// ---------------------------------------------------------------------------
// Decode kernel: sniff the storage layout of is_dominant and partner_idx.
//   is_dominant may arrive as u8 bool / int32 / int64 / float32 (0/1 values).
//   partner_idx may arrive as int32 / int64 / float32 (values in [0,128)).
// Detection uses byte/word patterns over the 128 entries; false-positive
// probability is negligible for random scenario assignments.
// 1 block, 128 threads.
// ---------------------------------------------------------------------------
__global__ __launch_bounds__(BB) void decode_kernel(const void* dom_raw,
                                                    const void* part_raw)
{
    const int b = threadIdx.x;

    const unsigned char* du8  = (const unsigned char*)dom_raw;
    const int*           di32 = (const int*)dom_raw;
    const long long*     di64 = (const long long*)dom_raw;
    const float*         df32 = (const float*)dom_raw;

    __shared__ int s_dflags;  // bit0: any byte set, bit1: set at b%4!=0,
                              // bit2: set at b%8!=0, bit3: f32 value == 1.0
    __shared__ int s_pflags;  // bit0: odd-index i32 nonzero, bit1: f32 plausible
    if (b == 0) { s_dflags = 0; s_pflags = 0; }
    __syncthreads();

    // --- is_dominant layout ---
    {
        int fl = 0;
        unsigned char byte_b = du8[b];  // first 128 bytes valid in every layout
        if (byte_b) { fl |= 1; if (b & 3) fl |= 2; if (b & 7) fl |= 4; }
        // f32 storage check: bit pattern 1.0f cannot arise from packed 0/1
        // bytes or 0/1 int words. Only first 32 f32 words are safely in
        // bounds under the smallest (u8) layout.
        if (b < 32 && df32[b] == 1.0f) fl |= 8;
        if (fl) atomicOr(&s_dflags, fl);
    }

    // --- partner_idx layout ---
    {
        const int*   pi32 = (const int*)part_raw;
        const float* pf32 = (const float*)part_raw;
        int fl = 0;
        if ((b & 1) && pi32[b] != 0) fl |= 1;   // odd-index i32 nonzero => i32
        if (b < 32) {                           // f32 check within min bounds
            float v = pf32[b];
            if (v >= 1.0f && v < 128.0f && v == rintf(v)) fl |= 2;
        }
        if (fl) atomicOr(&s_pflags, fl);
    }
    __syncthreads();

    // Normalize dominance.
    {
        const int f = s_dflags;
        int dom;
        if      (f & 8) dom = (df32[b] != 0.0f);          // float32
        else if (f & 2) dom = (du8[b]  != 0);             // u8 bool
        else if (f & 4) dom = (di32[b] != 0);             // int32
        else if (f & 1) dom = (di64[b] != 0);             // int64
        else            dom = 0;                          // nothing set anywhere
        g_dom[b] = dom;
    }

    // Normalize partner index.
    {
        const int*       pi32 = (const int*)part_raw;
        const long long* pi64 = (const long long*)part_raw;
        const float*     pf32 = (const float*)part_raw;
        const int f = s_pflags;
        int p;
        if      (f & 2) p = (int)pf32[b];                 // float32
        else if (f & 1) p = pi32[b];                      // int32
        else            p = (int)pi64[b];                 // int64
        if (p < 0 || p >= BB) p = b;                      // safety clamp
        g_partner[b] = p;
    }
}

// ---------------------------------------------------------------------------
// Kernel 1: per-(b,d) importance reduction over T, per-b 0.9-quantile via
// bitonic sort in shared memory, mask packed via ballot.
// One block per batch b, 512 threads (thread = d).
// ---------------------------------------------------------------------------
__global__ __launch_bounds__(DD) void im_mask_kernel(
    const float* __restrict__ x, const float* __restrict__ grad)
{
    const int b = blockIdx.x;
    const int d = threadIdx.x;

    const float* __restrict__ xb = x    + (size_t)b * TT * DD + d;
    const float* __restrict__ gb = grad + (size_t)b * TT * DD + d;

    // 4 independent accumulators -> MLP for the strided column walk.
    float a0 = 0.f, a1 = 0.f, a2 = 0.f, a3 = 0.f;
    #pragma unroll 4
    for (int t = 0; t < TT; t += 4) {
        a0 = fmaf(__ldg(gb + (size_t)(t + 0) * DD), __ldg(xb + (size_t)(t + 0) * DD), a0);
        a1 = fmaf(__ldg(gb + (size_t)(t + 1) * DD), __ldg(xb + (size_t)(t + 1) * DD), a1);
        a2 = fmaf(__ldg(gb + (size_t)(t + 2) * DD), __ldg(xb + (size_t)(t + 2) * DD), a2);
        a3 = fmaf(__ldg(gb + (size_t)(t + 3) * DD), __ldg(xb + (size_t)(t + 3) * DD), a3);
    }
    const float im = ((a0 + a1) + (a2 + a3)) * (1.0f / (float)TT);

    __shared__ float s[DD];
    s[d] = im;
    __syncthreads();

    // Bitonic sort (ascending), 512 elements, 512 threads.
    for (int k = 2; k <= DD; k <<= 1) {
        for (int j = k >> 1; j > 0; j >>= 1) {
            int ixj = d ^ j;
            if (ixj > d) {
                float va = s[d], vb = s[ixj];
                bool up = ((d & k) == 0);
                if ((va > vb) == up) { s[d] = vb; s[ixj] = va; }
            }
            __syncthreads();
        }
    }

    // jnp.quantile(q=0.9, linear): idx = 0.9*(512-1) = 459.9
    __shared__ float thr_sh;
    if (d == 0) {
        float lo = s[459], hi = s[460];
        thr_sh = lo + 0.9f * (hi - lo);
    }
    __syncthreads();
    const float thr = thr_sh;

    unsigned int bal = __ballot_sync(0xFFFFFFFFu, im > thr);
    if ((d & 31) == 0) g_mask[b][d >> 5] = bal;
}

// ---------------------------------------------------------------------------
// Kernel 2: apply. out[b,t,:] = x            (non-dominant, exact)
//                  out[b,t,:] = A*x + C*x_p  (dominant)
// A = mask_b ? m : 1 ; C = mask_p ? (1-m) : 0
// Grid (T, B), 128 threads, float4 per thread. Branch is uniform per block.
// ---------------------------------------------------------------------------
__global__ __launch_bounds__(128) void apply_kernel(
    const float* __restrict__ x,
    const float* __restrict__ mix,
    float* __restrict__ out)
{
    const int t   = blockIdx.x;
    const int b   = blockIdx.y;
    const int tid = threadIdx.x;

    const size_t row = ((size_t)b * TT + t) * DD;
    float4 xv = reinterpret_cast<const float4*>(x + row)[tid];
    float4 o;

    if (!g_dom[b]) {
        o = xv;  // sg + sr == x exactly for a 0/1 mask
    } else {
        const int   p  = g_partner[b];
        const float m  = mix[b];
        const float om = 1.0f - m;

        const size_t prow = ((size_t)p * TT + t) * DD;
        float4 xp = reinterpret_cast<const float4*>(x + prow)[tid];

        const int d0 = tid * 4;
        const unsigned mb = (g_mask[b][d0 >> 5] >> (d0 & 31)) & 0xFu;
        const unsigned mp = (g_mask[p][d0 >> 5] >> (d0 & 31)) & 0xFu;

        o.x = ((mb & 1u) ? m : 1.0f) * xv.x + ((mp & 1u) ? om : 0.0f) * xp.x;
        o.y = ((mb & 2u) ? m : 1.0f) * xv.y + ((mp & 2u) ? om : 0.0f) * xp.y;
        o.z = ((mb & 4u) ? m : 1.0f) * xv.z + ((mp & 4u) ? om : 0.0f) * xp.z;
        o.w = ((mb & 8u) ? m : 1.0f) * xv.w + ((mp & 8u) ? om : 0.0f) * xp.w;
    }

    reinterpret_cast<float4*>(out + row)[tid] = o;
}

// ---------------------------------------------------------------------------
// Inputs (metadata order): x, scenario_gradient, mixup_strength, scenario,
// partner_idx, is_dominant. Output: f32 B*T*D.
// ---------------------------------------------------------------------------
extern "C" void kernel_launch(void* const* d_in, const int* in_sizes, int n_in,
                              void* d_out, int out_size)
{
    const float* x    = (const float*)d_in[0];
    const float* grad = (const float*)d_in[1];
    const float* mix  = (const float*)d_in[2];
    // d_in[3] = scenario (unused)
    const void*  part = d_in[4];
    const void*  dom  = (n_in >= 6) ? d_in[5] : d_in[4];
    float*       out  = (float*)d_out;

    decode_kernel<<<1, BB>>>(dom, part);
    im_mask_kernel<<<BB, DD>>>(x, grad);

    dim3 grid(TT, BB);
    apply_kernel<<<grid, 128>>>(x, mix, out);
}

// round 3
// speedup vs baseline: 1.0299x; 1.0299x over previous
#include <cuda_runtime.h>
#include <cstdint>

#define BB 128
#define TT 1024
#define DD 512

// Packed significant-region mask: 512 bits per batch.
__device__ unsigned int g_mask[BB][DD / 32];
// Normalized metadata (decoded from whatever storage layout the harness used).
__device__ int g_dom[BB];
__device__ int g_partner[BB];

// ---------------------------------------------------------------------------
// Kernel 1: metadata decode (block 0 only) + per-(b,d) importance reduction
// over T (float4, 4 t-groups x 128 d-groups), per-b 0.9-quantile via bitonic
// sort, mask packed via ballot. One block per batch b, 512 threads.
// ---------------------------------------------------------------------------
__global__ __launch_bounds__(DD) void im_mask_kernel(
    const float* __restrict__ x, const float* __restrict__ grad,
    const void* dom_raw, const void* part_raw)
{
    const int b   = blockIdx.x;
    const int tid = threadIdx.x;

    // ---- decode (block 0 only; all 512 threads hit the syncs) -------------
    __shared__ int s_dflags, s_pflags;
    if (b == 0) {
        if (tid == 0) { s_dflags = 0; s_pflags = 0; }
        __syncthreads();
        if (tid < BB) {
            const unsigned char* du8  = (const unsigned char*)dom_raw;
            const float*         df32 = (const float*)dom_raw;
            int fl = 0;
            if (du8[tid]) { fl |= 1; if (tid & 3) fl |= 2; if (tid & 7) fl |= 4; }
            if (tid < 32 && df32[tid] == 1.0f) fl |= 8;  // f32 storage signature
            if (fl) atomicOr(&s_dflags, fl);

            const int*   pi32 = (const int*)part_raw;
            const float* pf32 = (const float*)part_raw;
            int pf = 0;
            if ((tid & 1) && pi32[tid] != 0) pf |= 1;    // odd-index i32 nonzero
            if (tid < 32) {
                float v = pf32[tid];
                if (v >= 1.0f && v < 128.0f && v == rintf(v)) pf |= 2;
            }
            if (pf) atomicOr(&s_pflags, pf);
        }
        __syncthreads();
        if (tid < BB) {
            const unsigned char* du8  = (const unsigned char*)dom_raw;
            const int*           di32 = (const int*)dom_raw;
            const long long*     di64 = (const long long*)dom_raw;
            const float*         df32 = (const float*)dom_raw;
            const int f = s_dflags;
            int dom;
            if      (f & 8) dom = (df32[tid] != 0.0f);
            else if (f & 2) dom = (du8[tid]  != 0);
            else if (f & 4) dom = (di32[tid] != 0);
            else if (f & 1) dom = (di64[tid] != 0);
            else            dom = 0;
            g_dom[tid] = dom;

            const int*       pi32 = (const int*)part_raw;
            const long long* pi64 = (const long long*)part_raw;
            const float*     pf32 = (const float*)part_raw;
            const int pfl = s_pflags;
            int p;
            if      (pfl & 2) p = (int)pf32[tid];
            else if (pfl & 1) p = pi32[tid];
            else              p = (int)pi64[tid];
            if (p < 0 || p >= BB) p = tid;
            g_partner[tid] = p;
        }
    }

    // ---- reduction: thread (tg, dg), tg = tid>>7 in [0,4), dg = tid&127 ---
    const int tg = tid >> 7;
    const int dg = tid & 127;

    const float4* __restrict__ x4 = (const float4*)(x    + (size_t)b * TT * DD);
    const float4* __restrict__ g4 = (const float4*)(grad + (size_t)b * TT * DD);

    float4 acc = make_float4(0.f, 0.f, 0.f, 0.f);
    size_t idx = (size_t)tg * 128 + dg;   // row stride in float4 = 128
    #pragma unroll 8
    for (int k = 0; k < TT / 4; ++k) {
        float4 xv = __ldg(&x4[idx]);
        float4 gv = __ldg(&g4[idx]);
        acc.x = fmaf(gv.x, xv.x, acc.x);
        acc.y = fmaf(gv.y, xv.y, acc.y);
        acc.z = fmaf(gv.z, xv.z, acc.z);
        acc.w = fmaf(gv.w, xv.w, acc.w);
        idx += 512;                       // skip 4 rows
    }

    __shared__ float4 s4[DD];             // [tg*128 + dg]
    __shared__ float  s[DD];
    s4[tid] = acc;
    __syncthreads();

    // im[d] = (Σ_tg partial) / T ; flat view: sf[tg*512 + d]
    const float* sf = (const float*)s4;
    const float im = (sf[tid] + sf[512 + tid] + sf[1024 + tid] + sf[1536 + tid])
                     * (1.0f / (float)TT);
    __syncthreads();
    s[tid] = im;
    __syncthreads();

    // Bitonic sort (ascending), 512 elements, 512 threads.
    for (int k = 2; k <= DD; k <<= 1) {
        for (int j = k >> 1; j > 0; j >>= 1) {
            int ixj = tid ^ j;
            if (ixj > tid) {
                float va = s[tid], vb = s[ixj];
                bool up = ((tid & k) == 0);
                if ((va > vb) == up) { s[tid] = vb; s[ixj] = va; }
            }
            __syncthreads();
        }
    }

    // jnp.quantile(q=0.9, linear): idx = 0.9*(512-1) = 459.9
    __shared__ float thr_sh;
    if (tid == 0) {
        float lo = s[459], hi = s[460];
        thr_sh = lo + 0.9f * (hi - lo);
    }
    __syncthreads();
    const float thr = thr_sh;

    unsigned int bal = __ballot_sync(0xFFFFFFFFu, im > thr);
    if ((tid & 31) == 0) g_mask[b][tid >> 5] = bal;
}

// ---------------------------------------------------------------------------
// Kernel 2: apply. Grid (B, 8 t-chunks), 256 threads. Block = 128 t-rows of
// batch b. Batch-fastest grid order -> same t-chunk co-resident across b ->
// partner reads hit L2. Coefficient float4 tables precomputed in shared.
//   out = A*x + C*x_p ;  A = mask_b ? m : 1 ; C = mask_p ? (1-m) : 0
// Non-dominant blocks are a pure copy (exact).
// ---------------------------------------------------------------------------
__global__ __launch_bounds__(256) void apply_kernel(
    const float* __restrict__ x,
    const float* __restrict__ mix,
    float* __restrict__ out)
{
    const int b   = blockIdx.x;
    const int ch  = blockIdx.y;
    const int tid = threadIdx.x;

    __shared__ float4 aco[128], cco[128];
    __shared__ int s_dom, s_p;
    __shared__ float s_m;
    if (tid == 0) { s_dom = g_dom[b]; s_p = g_partner[b]; s_m = mix[b]; }
    __syncthreads();

    const size_t base = ((size_t)b * TT + (size_t)ch * 128) * 128;  // float4 units
    const float4* __restrict__ x4 = (const float4*)x;
    float4* __restrict__ o4 = (float4*)out;

    if (!s_dom) {
        #pragma unroll 4
        for (int i = tid; i < 128 * 128; i += 256)
            o4[base + i] = __ldg(&x4[base + i]);
        return;
    }

    const int   p  = s_p;
    const float m  = s_m;
    const float om = 1.0f - m;

    if (tid < 128) {
        const int d0 = tid * 4;
        const unsigned wb = g_mask[b][d0 >> 5] >> (d0 & 31);
        const unsigned wp = g_mask[p][d0 >> 5] >> (d0 & 31);
        float4 a, c;
        a.x = (wb & 1u) ? m : 1.0f;  c.x = (wp & 1u) ? om : 0.0f;
        a.y = (wb & 2u) ? m : 1.0f;  c.y = (wp & 2u) ? om : 0.0f;
        a.z = (wb & 4u) ? m : 1.0f;  c.z = (wp & 4u) ? om : 0.0f;
        a.w = (wb & 8u) ? m : 1.0f;  c.w = (wp & 8u) ? om : 0.0f;
        aco[tid] = a;  cco[tid] = c;
    }
    __syncthreads();

    const size_t pbase = ((size_t)p * TT + (size_t)ch * 128) * 128;
    #pragma unroll 4
    for (int i = tid; i < 128 * 128; i += 256) {
        float4 xv = __ldg(&x4[base + i]);
        float4 xp = __ldg(&x4[pbase + i]);
        float4 a  = aco[i & 127];
        float4 c  = cco[i & 127];
        float4 o;
        o.x = a.x * xv.x + c.x * xp.x;
        o.y = a.y * xv.y + c.y * xp.y;
        o.z = a.z * xv.z + c.z * xp.z;
        o.w = a.w * xv.w + c.w * xp.w;
        o4[base + i] = o;
    }
}

// ---------------------------------------------------------------------------
// Inputs (metadata order): x, scenario_gradient, mixup_strength, scenario,
// partner_idx, is_dominant. Output: f32 B*T*D.
// ---------------------------------------------------------------------------
extern "C" void kernel_launch(void* const* d_in, const int* in_sizes, int n_in,
                              void* d_out, int out_size)
{
    const float* x    = (const float*)d_in[0];
    const float* grad = (const float*)d_in[1];
    const float* mix  = (const float*)d_in[2];
    // d_in[3] = scenario (unused)
    const void*  part = d_in[4];
    const void*  dom  = (n_in >= 6) ? d_in[5] : d_in[4];
    float*       out  = (float*)d_out;

    im_mask_kernel<<<BB, DD>>>(x, grad, dom, part);

    dim3 grid(BB, TT / 128);
    apply_kernel<<<grid, 256>>>(x, mix, out);
}

// round 4
// speedup vs baseline: 1.1701x; 1.1361x over previous
#include <cuda_runtime.h>
#include <cstdint>

#define BB 128
#define TT 1024
#define DD 512
#define QQ 8          // t-chunks per batch in the partial-reduction kernel

// Packed significant-region mask: 512 bits per batch.
__device__ unsigned int g_mask[BB][DD / 32];
// Partial per-(b,d) sums from the split reduction: [b][q][d].
__device__ float g_partial[BB][QQ][DD];
// Normalized metadata (decoded from whatever storage layout the harness used).
__device__ int g_dom[BB];
__device__ int g_partner[BB];

// ---------------------------------------------------------------------------
// Kernel A: partial reduction. Grid = B*QQ CTAs, 512 threads.
// CTA (b,q) covers rows [q*128, q*128+128) of batch b (0.5 MB x + 0.5 MB grad).
// Thread layout: 4 t-subgroups x 128 d-groups, float4. Cross-subgroup sum in
// shared memory; writes 512 partial d-sums to g_partial[b][q][:].
// ---------------------------------------------------------------------------
__global__ __launch_bounds__(DD) void partial_kernel(
    const float* __restrict__ x, const float* __restrict__ grad)
{
    const int c   = blockIdx.x;
    const int b   = c >> 3;
    const int q   = c & 7;
    const int tid = threadIdx.x;
    const int tg  = tid >> 7;       // 0..3
    const int dg  = tid & 127;      // 0..127 (float4 column)

    const size_t base = ((size_t)b * TT + (size_t)q * 128) * 128; // float4 units
    const float4* __restrict__ x4 = (const float4*)x;
    const float4* __restrict__ g4 = (const float4*)grad;

    float4 acc = make_float4(0.f, 0.f, 0.f, 0.f);
    size_t idx = base + (size_t)tg * 128 + dg;
    #pragma unroll 8
    for (int k = 0; k < 32; ++k) {          // 32 * 4 rows = 128 rows
        float4 xv = __ldg(&x4[idx]);
        float4 gv = __ldcs(&g4[idx]);       // grad never reused: evict-first
        acc.x = fmaf(gv.x, xv.x, acc.x);
        acc.y = fmaf(gv.y, xv.y, acc.y);
        acc.z = fmaf(gv.z, xv.z, acc.z);
        acc.w = fmaf(gv.w, xv.w, acc.w);
        idx += 512;                         // skip 4 rows
    }

    __shared__ float4 s4[DD];               // [tg*128 + dg]
    s4[tid] = acc;
    __syncthreads();

    // flat view: sf[tg*512 + d]
    const float* sf = (const float*)s4;
    g_partial[b][q][tid] = sf[tid] + sf[512 + tid] + sf[1024 + tid] + sf[1536 + tid];
}

// ---------------------------------------------------------------------------
// Kernel B: mask + metadata decode. 128 blocks x 512 threads.
// im[d] = sum_q partial / T ; 0.9-quantile via bitonic sort; ballot-packed mask.
// Block 0 additionally decodes is_dominant / partner_idx storage layouts.
// ---------------------------------------------------------------------------
__global__ __launch_bounds__(DD) void mask_kernel(
    const void* dom_raw, const void* part_raw)
{
    const int b   = blockIdx.x;
    const int tid = threadIdx.x;

    // ---- decode (block 0 only) --------------------------------------------
    __shared__ int s_dflags, s_pflags;
    if (b == 0) {
        if (tid == 0) { s_dflags = 0; s_pflags = 0; }
        __syncthreads();
        if (tid < BB) {
            const unsigned char* du8  = (const unsigned char*)dom_raw;
            const float*         df32 = (const float*)dom_raw;
            int fl = 0;
            if (du8[tid]) { fl |= 1; if (tid & 3) fl |= 2; if (tid & 7) fl |= 4; }
            if (tid < 32 && df32[tid] == 1.0f) fl |= 8;   // f32 storage signature
            if (fl) atomicOr(&s_dflags, fl);

            const int*   pi32 = (const int*)part_raw;
            const float* pf32 = (const float*)part_raw;
            int pf = 0;
            if ((tid & 1) && pi32[tid] != 0) pf |= 1;     // odd-index i32 nonzero
            if (tid < 32) {
                float v = pf32[tid];
                if (v >= 1.0f && v < 128.0f && v == rintf(v)) pf |= 2;
            }
            if (pf) atomicOr(&s_pflags, pf);
        }
        __syncthreads();
        if (tid < BB) {
            const unsigned char* du8  = (const unsigned char*)dom_raw;
            const int*           di32 = (const int*)dom_raw;
            const long long*     di64 = (const long long*)dom_raw;
            const float*         df32 = (const float*)dom_raw;
            const int f = s_dflags;
            int dom;
            if      (f & 8) dom = (df32[tid] != 0.0f);
            else if (f & 2) dom = (du8[tid]  != 0);
            else if (f & 4) dom = (di32[tid] != 0);
            else if (f & 1) dom = (di64[tid] != 0);
            else            dom = 0;
            g_dom[tid] = dom;

            const int*       pi32 = (const int*)part_raw;
            const long long* pi64 = (const long long*)part_raw;
            const float*     pf32 = (const float*)part_raw;
            const int pfl = s_pflags;
            int p;
            if      (pfl & 2) p = (int)pf32[tid];
            else if (pfl & 1) p = pi32[tid];
            else              p = (int)pi64[tid];
            if (p < 0 || p >= BB) p = tid;
            g_partner[tid] = p;
        }
    }

    // ---- im from partials (L2-resident) ------------------------------------
    float sum = 0.f;
    #pragma unroll
    for (int q = 0; q < QQ; ++q) sum += g_partial[b][q][tid];
    const float im = sum * (1.0f / (float)TT);

    __shared__ float s[DD];
    s[tid] = im;
    __syncthreads();

    // Bitonic sort (ascending), 512 elements, 512 threads.
    for (int k = 2; k <= DD; k <<= 1) {
        for (int j = k >> 1; j > 0; j >>= 1) {
            int ixj = tid ^ j;
            if (ixj > tid) {
                float va = s[tid], vb = s[ixj];
                bool up = ((tid & k) == 0);
                if ((va > vb) == up) { s[tid] = vb; s[ixj] = va; }
            }
            __syncthreads();
        }
    }

    // jnp.quantile(q=0.9, linear): idx = 0.9*(512-1) = 459.9
    __shared__ float thr_sh;
    if (tid == 0) {
        float lo = s[459], hi = s[460];
        thr_sh = lo + 0.9f * (hi - lo);
    }
    __syncthreads();
    const float thr = thr_sh;

    unsigned int bal = __ballot_sync(0xFFFFFFFFu, im > thr);
    if ((tid & 31) == 0) g_mask[b][tid >> 5] = bal;
}

// ---------------------------------------------------------------------------
// Kernel C: apply. Grid (B, 8 t-chunks), 256 threads. Batch-fastest grid
// order -> same t-chunk co-resident across b -> partner reads hit L2.
//   out = A*x + C*x_p ;  A = mask_b ? m : 1 ; C = mask_p ? (1-m) : 0
// Non-dominant blocks are a pure copy (exact). Evict-first stores.
// ---------------------------------------------------------------------------
__global__ __launch_bounds__(256) void apply_kernel(
    const float* __restrict__ x,
    const float* __restrict__ mix,
    float* __restrict__ out)
{
    const int b   = blockIdx.x;
    const int ch  = blockIdx.y;
    const int tid = threadIdx.x;

    __shared__ float4 aco[128], cco[128];
    __shared__ int s_dom, s_p;
    __shared__ float s_m;
    if (tid == 0) { s_dom = g_dom[b]; s_p = g_partner[b]; s_m = mix[b]; }
    __syncthreads();

    const size_t base = ((size_t)b * TT + (size_t)ch * 128) * 128;  // float4 units
    const float4* __restrict__ x4 = (const float4*)x;
    float4* __restrict__ o4 = (float4*)out;

    if (!s_dom) {
        #pragma unroll 8
        for (int i = tid; i < 128 * 128; i += 256)
            __stcs(&o4[base + i], __ldg(&x4[base + i]));
        return;
    }

    const int   p  = s_p;
    const float m  = s_m;
    const float om = 1.0f - m;

    if (tid < 128) {
        const int d0 = tid * 4;
        const unsigned wb = g_mask[b][d0 >> 5] >> (d0 & 31);
        const unsigned wp = g_mask[p][d0 >> 5] >> (d0 & 31);
        float4 a, c;
        a.x = (wb & 1u) ? m : 1.0f;  c.x = (wp & 1u) ? om : 0.0f;
        a.y = (wb & 2u) ? m : 1.0f;  c.y = (wp & 2u) ? om : 0.0f;
        a.z = (wb & 4u) ? m : 1.0f;  c.z = (wp & 4u) ? om : 0.0f;
        a.w = (wb & 8u) ? m : 1.0f;  c.w = (wp & 8u) ? om : 0.0f;
        aco[tid] = a;  cco[tid] = c;
    }
    __syncthreads();

    const size_t pbase = ((size_t)p * TT + (size_t)ch * 128) * 128;
    #pragma unroll 8
    for (int i = tid; i < 128 * 128; i += 256) {
        float4 xv = __ldg(&x4[base + i]);
        float4 xp = __ldg(&x4[pbase + i]);
        float4 a  = aco[i & 127];
        float4 c  = cco[i & 127];
        float4 o;
        o.x = a.x * xv.x + c.x * xp.x;
        o.y = a.y * xv.y + c.y * xp.y;
        o.z = a.z * xv.z + c.z * xp.z;
        o.w = a.w * xv.w + c.w * xp.w;
        __stcs(&o4[base + i], o);
    }
}

// ---------------------------------------------------------------------------
// Inputs (metadata order): x, scenario_gradient, mixup_strength, scenario,
// partner_idx, is_dominant. Output: f32 B*T*D.
// ---------------------------------------------------------------------------
extern "C" void kernel_launch(void* const* d_in, const int* in_sizes, int n_in,
                              void* d_out, int out_size)
{
    const float* x    = (const float*)d_in[0];
    const float* grad = (const float*)d_in[1];
    const float* mix  = (const float*)d_in[2];
    // d_in[3] = scenario (unused)
    const void*  part = d_in[4];
    const void*  dom  = (n_in >= 6) ? d_in[5] : d_in[4];
    float*       out  = (float*)d_out;

    partial_kernel<<<BB * QQ, DD>>>(x, grad);
    mask_kernel<<<BB, DD>>>(dom, part);

    dim3 grid(BB, TT / 128);
    apply_kernel<<<grid, 256>>>(x, mix, out);
}

// round 5
// speedup vs baseline: 1.2956x; 1.1072x over previous
#include <cuda_runtime.h>
#include <cstdint>

#define BB 128
#define TT 1024
#define DD 512
#define QQ 8          // t-chunks per batch in the partial-reduction kernel

// Packed significant-region mask: 512 bits per batch.
__device__ unsigned int g_mask[BB][DD / 32];
// Partial per-(b,d) sums from the split reduction: [b][q][d].
__device__ float g_partial[BB][QQ][DD];
// Completion counters for the fused mask step (reset to 0 by the consumer).
__device__ unsigned int g_count[BB];
// Normalized metadata (decoded from whatever storage layout the harness used).
__device__ int g_dom[BB];
__device__ int g_partner[BB];

// ---------------------------------------------------------------------------
// Kernel A: partial reduction + fused per-batch mask (threadfence reduction).
// Grid = B*QQ CTAs, 512 threads. CTA (b,q) covers rows [q*128, q*128+128).
// The last CTA to finish a batch sums the 8 partials, computes the 0.9-
// quantile via bitonic sort, ballots the packed mask, and resets the counter
// (so graph replays start clean). CTA 0 also decodes metadata layouts.
// ---------------------------------------------------------------------------
__global__ __launch_bounds__(DD) void partial_kernel(
    const float* __restrict__ x, const float* __restrict__ grad,
    const void* dom_raw, const void* part_raw)
{
    const int c   = blockIdx.x;
    const int b   = c >> 3;
    const int q   = c & 7;
    const int tid = threadIdx.x;
    const int tg  = tid >> 7;       // 0..3
    const int dg  = tid & 127;      // 0..127 (float4 column)

    // ---- decode (CTA 0 only; cheap, runs before its streaming loop) -------
    __shared__ int s_dflags, s_pflags;
    if (c == 0) {
        if (tid == 0) { s_dflags = 0; s_pflags = 0; }
        __syncthreads();
        if (tid < BB) {
            const unsigned char* du8  = (const unsigned char*)dom_raw;
            const float*         df32 = (const float*)dom_raw;
            int fl = 0;
            if (du8[tid]) { fl |= 1; if (tid & 3) fl |= 2; if (tid & 7) fl |= 4; }
            if (tid < 32 && df32[tid] == 1.0f) fl |= 8;   // f32 storage signature
            if (fl) atomicOr(&s_dflags, fl);

            const int*   pi32 = (const int*)part_raw;
            const float* pf32 = (const float*)part_raw;
            int pf = 0;
            if ((tid & 1) && pi32[tid] != 0) pf |= 1;     // odd-index i32 nonzero
            if (tid < 32) {
                float v = pf32[tid];
                if (v >= 1.0f && v < 128.0f && v == rintf(v)) pf |= 2;
            }
            if (pf) atomicOr(&s_pflags, pf);
        }
        __syncthreads();
        if (tid < BB) {
            const unsigned char* du8  = (const unsigned char*)dom_raw;
            const int*           di32 = (const int*)dom_raw;
            const long long*     di64 = (const long long*)dom_raw;
            const float*         df32 = (const float*)dom_raw;
            const int f = s_dflags;
            int dom;
            if      (f & 8) dom = (df32[tid] != 0.0f);
            else if (f & 2) dom = (du8[tid]  != 0);
            else if (f & 4) dom = (di32[tid] != 0);
            else if (f & 1) dom = (di64[tid] != 0);
            else            dom = 0;
            g_dom[tid] = dom;

            const int*       pi32 = (const int*)part_raw;
            const long long* pi64 = (const long long*)part_raw;
            const float*     pf32 = (const float*)part_raw;
            const int pfl = s_pflags;
            int p;
            if      (pfl & 2) p = (int)pf32[tid];
            else if (pfl & 1) p = pi32[tid];
            else              p = (int)pi64[tid];
            if (p < 0 || p >= BB) p = tid;
            g_partner[tid] = p;
        }
        __syncthreads();
    }

    // ---- streaming partial reduction ---------------------------------------
    const size_t base = ((size_t)b * TT + (size_t)q * 128) * 128; // float4 units
    const float4* __restrict__ x4 = (const float4*)x;
    const float4* __restrict__ g4 = (const float4*)grad;

    float4 acc = make_float4(0.f, 0.f, 0.f, 0.f);
    size_t idx = base + (size_t)tg * 128 + dg;
    #pragma unroll 8
    for (int k = 0; k < 32; ++k) {          // 32 * 4 rows = 128 rows
        float4 xv = __ldg(&x4[idx]);
        float4 gv = __ldcs(&g4[idx]);       // grad never reused: evict-first
        acc.x = fmaf(gv.x, xv.x, acc.x);
        acc.y = fmaf(gv.y, xv.y, acc.y);
        acc.z = fmaf(gv.z, xv.z, acc.z);
        acc.w = fmaf(gv.w, xv.w, acc.w);
        idx += 512;                         // skip 4 rows
    }

    __shared__ float4 s4[DD];               // [tg*128 + dg]
    s4[tid] = acc;
    __syncthreads();

    // flat view: sf[tg*512 + d]
    const float* sf = (const float*)s4;
    g_partial[b][q][tid] = sf[tid] + sf[512 + tid] + sf[1024 + tid] + sf[1536 + tid];

    // ---- elect the last CTA of this batch to finish the mask ---------------
    __threadfence();                         // make partials visible device-wide
    __shared__ int s_last;
    __syncthreads();                         // all partial writes issued
    if (tid == 0) {
        unsigned int prev = atomicAdd(&g_count[b], 1u);
        s_last = (prev == QQ - 1);
    }
    __syncthreads();
    if (!s_last) return;

    // im[d] = (sum_q partial) / T
    float sum = 0.f;
    #pragma unroll
    for (int qq = 0; qq < QQ; ++qq) sum += g_partial[b][qq][tid];
    const float im = sum * (1.0f / (float)TT);

    __shared__ float s[DD];
    __syncthreads();
    s[tid] = im;
    __syncthreads();

    // Bitonic sort (ascending), 512 elements, 512 threads.
    for (int k = 2; k <= DD; k <<= 1) {
        for (int j = k >> 1; j > 0; j >>= 1) {
            int ixj = tid ^ j;
            if (ixj > tid) {
                float va = s[tid], vb = s[ixj];
                bool up = ((tid & k) == 0);
                if ((va > vb) == up) { s[tid] = vb; s[ixj] = va; }
            }
            __syncthreads();
        }
    }

    // jnp.quantile(q=0.9, linear): idx = 0.9*(512-1) = 459.9
    __shared__ float thr_sh;
    if (tid == 0) {
        float lo = s[459], hi = s[460];
        thr_sh = lo + 0.9f * (hi - lo);
        g_count[b] = 0;                      // reset for next graph replay
    }
    __syncthreads();
    const float thr = thr_sh;

    unsigned int bal = __ballot_sync(0xFFFFFFFFu, im > thr);
    if ((tid & 31) == 0) g_mask[b][tid >> 5] = bal;
}

// ---------------------------------------------------------------------------
// Kernel B: apply. Grid (B, 16 t-chunks), 512 threads. Block = 64 t-rows of
// batch b. Batch-fastest grid order -> same t-chunk co-resident across b ->
// partner reads hit L2. Coefficient float4 tables precomputed in shared.
//   out = A*x + C*x_p ;  A = mask_b ? m : 1 ; C = mask_p ? (1-m) : 0
// Non-dominant blocks are a pure copy (exact). Evict-first stores.
// ---------------------------------------------------------------------------
__global__ __launch_bounds__(512) void apply_kernel(
    const float* __restrict__ x,
    const float* __restrict__ mix,
    float* __restrict__ out)
{
    const int b   = blockIdx.x;
    const int ch  = blockIdx.y;
    const int tid = threadIdx.x;

    __shared__ float4 aco[128], cco[128];
    __shared__ int s_dom, s_p;
    __shared__ float s_m;
    if (tid == 0) { s_dom = g_dom[b]; s_p = g_partner[b]; s_m = mix[b]; }
    __syncthreads();

    const size_t base = ((size_t)b * TT + (size_t)ch * 64) * 128;  // float4 units
    const float4* __restrict__ x4 = (const float4*)x;
    float4* __restrict__ o4 = (float4*)out;

    if (!s_dom) {
        #pragma unroll
        for (int i = tid; i < 64 * 128; i += 512)
            __stcs(&o4[base + i], __ldg(&x4[base + i]));
        return;
    }

    const int   p  = s_p;
    const float m  = s_m;
    const float om = 1.0f - m;

    if (tid < 128) {
        const int d0 = tid * 4;
        const unsigned wb = g_mask[b][d0 >> 5] >> (d0 & 31);
        const unsigned wp = g_mask[p][d0 >> 5] >> (d0 & 31);
        float4 a, c;
        a.x = (wb & 1u) ? m : 1.0f;  c.x = (wp & 1u) ? om : 0.0f;
        a.y = (wb & 2u) ? m : 1.0f;  c.y = (wp & 2u) ? om : 0.0f;
        a.z = (wb & 4u) ? m : 1.0f;  c.z = (wp & 4u) ? om : 0.0f;
        a.w = (wb & 8u) ? m : 1.0f;  c.w = (wp & 8u) ? om : 0.0f;
        aco[tid] = a;  cco[tid] = c;
    }
    __syncthreads();

    const size_t pbase = ((size_t)p * TT + (size_t)ch * 64) * 128;
    #pragma unroll
    for (int i = tid; i < 64 * 128; i += 512) {
        float4 xv = __ldg(&x4[base + i]);
        float4 xp = __ldg(&x4[pbase + i]);
        float4 a  = aco[i & 127];
        float4 c  = cco[i & 127];
        float4 o;
        o.x = a.x * xv.x + c.x * xp.x;
        o.y = a.y * xv.y + c.y * xp.y;
        o.z = a.z * xv.z + c.z * xp.z;
        o.w = a.w * xv.w + c.w * xp.w;
        __stcs(&o4[base + i], o);
    }
}

// ---------------------------------------------------------------------------
// Inputs (metadata order): x, scenario_gradient, mixup_strength, scenario,
// partner_idx, is_dominant. Output: f32 B*T*D.
// ---------------------------------------------------------------------------
extern "C" void kernel_launch(void* const* d_in, const int* in_sizes, int n_in,
                              void* d_out, int out_size)
{
    const float* x    = (const float*)d_in[0];
    const float* grad = (const float*)d_in[1];
    const float* mix  = (const float*)d_in[2];
    // d_in[3] = scenario (unused)
    const void*  part = d_in[4];
    const void*  dom  = (n_in >= 6) ? d_in[5] : d_in[4];
    float*       out  = (float*)d_out;

    partial_kernel<<<BB * QQ, DD>>>(x, grad, dom, part);

    dim3 grid(BB, TT / 64);
    apply_kernel<<<grid, 512>>>(x, mix, out);
}